// round 14
// baseline (speedup 1.0000x reference)
#include <cuda_runtime.h>
#include <cuda_bf16.h>
#include <stdint.h>

#define BBATCH 4
#define SEQ 2048
#define DIM 1024
#define NHEAD 16
#define HDIM 64
#define MROWS (BBATCH * SEQ)   // 8192

__device__ __nv_bfloat16 g_xh[3][MROWS * DIM];
__device__ __nv_bfloat16 g_xl[3][MROWS * DIM];
__device__ __nv_bfloat16 g_wh[4][DIM * DIM];
__device__ __nv_bfloat16 g_wl[4][DIM * DIM];
__device__ __nv_bfloat16 g_qh[BBATCH * NHEAD * SEQ * HDIM];  // [B,H,S,HD]
__device__ __nv_bfloat16 g_ql[BBATCH * NHEAD * SEQ * HDIM];
__device__ __nv_bfloat16 g_kh[BBATCH * NHEAD * SEQ * HDIM];
__device__ __nv_bfloat16 g_kl[BBATCH * NHEAD * SEQ * HDIM];
__device__ __nv_bfloat16 g_vh[BBATCH * NHEAD * HDIM * SEQ];  // [B,H,HD,S]
__device__ __nv_bfloat16 g_vl[BBATCH * NHEAD * HDIM * SEQ];
__device__ __nv_bfloat16 g_ath[BBATCH * SEQ * DIM];
__device__ __nv_bfloat16 g_atl[BBATCH * SEQ * DIM];

// ---------------------------------------------------------------------------
__device__ __forceinline__ uint32_t s2u(const void* p) {
    uint32_t a;
    asm("{ .reg .u64 t; cvta.to.shared.u64 t, %1; cvt.u32.u64 %0, t; }" : "=r"(a) : "l"(p));
    return a;
}
__device__ __forceinline__ float ex2f(float x) {
    float y;
    asm("ex2.approx.f32 %0, %1;" : "=f"(y) : "f"(x));
    return y;
}

#define LDSM4(r0, r1, r2, r3, a) \
    asm volatile("ldmatrix.sync.aligned.m8n8.x4.shared.b16 {%0,%1,%2,%3}, [%4];" \
                 : "=r"(r0), "=r"(r1), "=r"(r2), "=r"(r3) : "r"(a))

#define MMA16816(d, a0, a1, a2, a3, b0, b1) \
    asm volatile("mma.sync.aligned.m16n8k16.row.col.f32.bf16.bf16.f32 " \
                 "{%0,%1,%2,%3},{%4,%5,%6,%7},{%8,%9},{%0,%1,%2,%3};" \
                 : "+f"((d)[0]), "+f"((d)[1]), "+f"((d)[2]), "+f"((d)[3]) \
                 : "r"(a0), "r"(a1), "r"(a2), "r"(a3), "r"(b0), "r"(b1))

#define CP16(d, s) \
    asm volatile("cp.async.cg.shared.global [%0], [%1], 16;" :: "r"(d), "l"(s))
#define CP_COMMIT() asm volatile("cp.async.commit_group;" ::: "memory")
#define CP_WAIT(n)  asm volatile("cp.async.wait_group %0;" :: "n"(n) : "memory")

__device__ __forceinline__ void split2(float a, float b, uint32_t& h, uint32_t& l) {
    __nv_bfloat16 ha = __float2bfloat16_rn(a);
    __nv_bfloat16 hb = __float2bfloat16_rn(b);
    float la = a - __bfloat162float(ha);
    float lb = b - __bfloat162float(hb);
    __nv_bfloat162 H = __halves2bfloat162(ha, hb);
    __nv_bfloat162 L = __floats2bfloat162_rn(la, lb);
    h = *reinterpret_cast<uint32_t*>(&H);
    l = *reinterpret_cast<uint32_t*>(&L);
}
__device__ __forceinline__ void splitP(float a, float b, uint32_t& h, uint32_t& l) {
    const uint32_t ua = __float_as_uint(a), ub = __float_as_uint(b);
    h = __byte_perm(ua, ub, 0x7632);
    const float la = a - __uint_as_float(ua & 0xFFFF0000u);
    const float lb = b - __uint_as_float(ub & 0xFFFF0000u);
    __nv_bfloat162 L = __floats2bfloat162_rn(la, lb);
    l = *reinterpret_cast<uint32_t*>(&L);
}

// ---------------------------------------------------------------------------
__global__ __launch_bounds__(256)
void split_many(const float4* __restrict__ x0, const float4* __restrict__ x1,
                const float4* __restrict__ x2, const float4* __restrict__ x3,
                uint2* __restrict__ hb, uint2* __restrict__ lb, int n4)
{
    const int t = blockIdx.y;
    const float4* x = (t == 0) ? x0 : (t == 1) ? x1 : (t == 2) ? x2 : x3;
    uint2* h = hb + (size_t)t * n4;
    uint2* l = lb + (size_t)t * n4;
    for (int i = blockIdx.x * 256 + threadIdx.x; i < n4; i += gridDim.x * 256) {
        float4 v = x[i];
        uint2 hi, lo;
        split2(v.x, v.y, hi.x, lo.x);
        split2(v.z, v.w, hi.y, lo.y);
        h[i] = hi;
        l[i] = lo;
    }
}

// ---------------------------------------------------------------------------
// Split-bf16 GEMM body: tile 128x128, BK=64 (16 iterations -> half the
// barriers), 3-stage cp.async (192KB smem, occ 1), one sync/iter.
// Rows are 128B wide with (r&7)<<4 swizzle (same geometry as attention).
// ---------------------------------------------------------------------------
#define PROJ_STG 65536
#define PROJ_SMEM 196608
#define NIT 16

__device__ __forceinline__ void proj_body(
    const __nv_bfloat16* __restrict__ Xh, const __nv_bfloat16* __restrict__ Xl,
    const __nv_bfloat16* __restrict__ Wh, const __nv_bfloat16* __restrict__ Wl,
    const float* __restrict__ bias, void* outA, void* outB,
    int mode, float scale, char* smc)
{
    const uint32_t sb = s2u(smc);
    const int tid = threadIdx.x;
    const int wid = tid >> 5;
    const int lane = tid & 31;

    const int m0 = blockIdx.y * 128;
    const int n0 = blockIdx.x * 128;
    const int wm = wid & 1;
    const int wn = wid >> 1;

    // loader: array la_ = tid>>6 (Ah, Al, Bh, Bl); rows pr*2, pr*2+1 (128B each)
    const int la_ = tid >> 6;
    const int pr = tid & 63;
    const __nv_bfloat16* gp = (la_ == 0) ? Xh : (la_ == 1) ? Xl : (la_ == 2) ? Wh : Wl;
    const int rb = (la_ < 2) ? m0 : n0;
    const char* gsrc = (const char*)(gp + (size_t)(rb + pr * 2) * DIM);
    const uint32_t ld0 = sb + (uint32_t)la_ * 16384u + (uint32_t)(pr * 2) * 128u;
    const uint32_t sw0 = ((uint32_t)(pr * 2) & 7u) << 4;
    const uint32_t sw1 = ((uint32_t)(pr * 2 + 1) & 7u) << 4;

    // ldmatrix geometry (128B rows)
    const int a_rin = (lane & 7) + ((lane >> 3) & 1) * 8;
    const uint32_t a_cbs = (uint32_t)((lane >> 4) * 16);
    const int b_rin = (lane & 7) + (lane >> 4) * 8;
    const uint32_t b_cbs = (uint32_t)(((lane >> 3) & 1) * 16);

    uint32_t aoff[4], arx[4];
#pragma unroll
    for (int t = 0; t < 4; t++) {
        const uint32_t r = (uint32_t)(wm * 64 + t * 16 + a_rin);
        aoff[t] = r * 128u;
        arx[t] = (r & 7u) << 4;
    }
    uint32_t boff[2], brx[2];
#pragma unroll
    for (int u = 0; u < 2; u++) {
        const uint32_t r = (uint32_t)(wn * 32 + u * 16 + b_rin);
        boff[u] = r * 128u;
        brx[u] = (r & 7u) << 4;
    }

    float acc[4][4][4];
#pragma unroll
    for (int i = 0; i < 4; i++)
#pragma unroll
        for (int j = 0; j < 4; j++)
#pragma unroll
            for (int c = 0; c < 4; c++) acc[i][j][c] = 0.f;

    // prologue: stages 0,1 (each 64 cols = 128B per row)
#pragma unroll
    for (int s = 0; s < 2; s++) {
        const char* s0 = gsrc + s * 128;
        const char* s1 = s0 + DIM * 2;
        const uint32_t d = ld0 + (uint32_t)(s * PROJ_STG);
#pragma unroll
        for (int i = 0; i < 8; i++) CP16(d + (((uint32_t)(i * 16)) ^ sw0), s0 + i * 16);
#pragma unroll
        for (int i = 0; i < 8; i++) CP16(d + 128u + (((uint32_t)(i * 16)) ^ sw1), s1 + i * 16);
        CP_COMMIT();
    }

    int stg = 0;
    for (int it = 0; it < NIT; it++) {
        if (it == NIT - 1) { CP_WAIT(0); } else { CP_WAIT(1); }
        __syncthreads();

        const uint32_t st = sb + (uint32_t)(stg * PROJ_STG);
        const uint32_t sAh = st, sAl = st + 16384u, sBh = st + 32768u, sBl = st + 49152u;

        // ---- kk = 0: LDSM ----
        uint32_t bh[2][4], bl[2][4], ah[4][4], al[4][4];
#pragma unroll
        for (int u = 0; u < 2; u++) {
            const uint32_t ad = boff[u] + (b_cbs ^ brx[u]);
            LDSM4(bh[u][0], bh[u][1], bh[u][2], bh[u][3], sBh + ad);
            LDSM4(bl[u][0], bl[u][1], bl[u][2], bl[u][3], sBl + ad);
        }
#pragma unroll
        for (int t = 0; t < 4; t++) {
            const uint32_t ad = aoff[t] + (a_cbs ^ arx[t]);
            LDSM4(ah[t][0], ah[t][1], ah[t][2], ah[t][3], sAh + ad);
            LDSM4(al[t][0], al[t][1], al[t][2], al[t][3], sAl + ad);
        }

        // prefetch stage it+2 (between LDSM(kk0) and MMA(kk0), as in R7)
        if (it + 2 < NIT) {
            const char* s0 = gsrc + (it + 2) * 128;
            const char* s1 = s0 + DIM * 2;
            const uint32_t d = ld0 + (uint32_t)(((it + 2) % 3) * PROJ_STG);
#pragma unroll
            for (int i = 0; i < 8; i++) CP16(d + (((uint32_t)(i * 16)) ^ sw0), s0 + i * 16);
#pragma unroll
            for (int i = 0; i < 8; i++) CP16(d + 128u + (((uint32_t)(i * 16)) ^ sw1), s1 + i * 16);
            CP_COMMIT();
        }

        // ---- kk = 0: MMA ----
#pragma unroll
        for (int t = 0; t < 4; t++)
#pragma unroll
            for (int nt = 0; nt < 4; nt++) {
                const int u = nt >> 1, h2 = (nt & 1) * 2;
                MMA16816(acc[t][nt], ah[t][0], ah[t][1], ah[t][2], ah[t][3],
                         bh[u][h2], bh[u][h2 + 1]);
                MMA16816(acc[t][nt], ah[t][0], ah[t][1], ah[t][2], ah[t][3],
                         bl[u][h2], bl[u][h2 + 1]);
                MMA16816(acc[t][nt], al[t][0], al[t][1], al[t][2], al[t][3],
                         bh[u][h2], bh[u][h2 + 1]);
            }

        // ---- kk = 1..3 ----
#pragma unroll
        for (int kk = 1; kk < 4; kk++) {
#pragma unroll
            for (int u = 0; u < 2; u++) {
                const uint32_t ad = boff[u] + (((uint32_t)(kk * 32) + b_cbs) ^ brx[u]);
                LDSM4(bh[u][0], bh[u][1], bh[u][2], bh[u][3], sBh + ad);
                LDSM4(bl[u][0], bl[u][1], bl[u][2], bl[u][3], sBl + ad);
            }
#pragma unroll
            for (int t = 0; t < 4; t++) {
                const uint32_t ad = aoff[t] + (((uint32_t)(kk * 32) + a_cbs) ^ arx[t]);
                LDSM4(ah[t][0], ah[t][1], ah[t][2], ah[t][3], sAh + ad);
                LDSM4(al[t][0], al[t][1], al[t][2], al[t][3], sAl + ad);
            }
#pragma unroll
            for (int t = 0; t < 4; t++)
#pragma unroll
                for (int nt = 0; nt < 4; nt++) {
                    const int u = nt >> 1, h2 = (nt & 1) * 2;
                    MMA16816(acc[t][nt], ah[t][0], ah[t][1], ah[t][2], ah[t][3],
                             bh[u][h2], bh[u][h2 + 1]);
                    MMA16816(acc[t][nt], ah[t][0], ah[t][1], ah[t][2], ah[t][3],
                             bl[u][h2], bl[u][h2 + 1]);
                    MMA16816(acc[t][nt], al[t][0], al[t][1], al[t][2], al[t][3],
                             bh[u][h2], bh[u][h2 + 1]);
                }
        }

        stg++;
        if (stg == 3) stg = 0;
    }

#pragma unroll
    for (int mt = 0; mt < 4; mt++) {
        const int m1 = m0 + wm * 64 + mt * 16 + (lane >> 2);
        const int m2 = m1 + 8;
#pragma unroll
        for (int nt = 0; nt < 4; nt++) {
            const int n = n0 + wn * 32 + nt * 8 + (lane & 3) * 2;
            const float b0v = bias[n], b1v = bias[n + 1];
            const float v00 = (acc[mt][nt][0] + b0v) * scale;
            const float v01 = (acc[mt][nt][1] + b1v) * scale;
            const float v10 = (acc[mt][nt][2] + b0v) * scale;
            const float v11 = (acc[mt][nt][3] + b1v) * scale;
            if (mode == 0) {
                float* out = (float*)outA;
                *(float2*)(out + (size_t)m1 * DIM + n) = make_float2(v00, v01);
                *(float2*)(out + (size_t)m2 * DIM + n) = make_float2(v10, v11);
            } else {
                const int h = n >> 6, hd = n & 63;
                const int b1i = m1 >> 11, s1 = m1 & 2047;
                const int b2i = m2 >> 11, s2 = m2 & 2047;
                __nv_bfloat16* oh = (__nv_bfloat16*)outA;
                __nv_bfloat16* ol = (__nv_bfloat16*)outB;
                if (mode == 1) {
                    uint32_t h0, l0, h1, l1;
                    split2(v00, v01, h0, l0);
                    split2(v10, v11, h1, l1);
                    const size_t i1 = (((size_t)b1i * NHEAD + h) * SEQ + s1) * HDIM + hd;
                    const size_t i2 = (((size_t)b2i * NHEAD + h) * SEQ + s2) * HDIM + hd;
                    *(uint32_t*)(oh + i1) = h0;
                    *(uint32_t*)(ol + i1) = l0;
                    *(uint32_t*)(oh + i2) = h1;
                    *(uint32_t*)(ol + i2) = l1;
                } else {
                    const size_t t1 = (((size_t)b1i * NHEAD + h) * HDIM + hd) * SEQ + s1;
                    const size_t t2 = (((size_t)b2i * NHEAD + h) * HDIM + hd) * SEQ + s2;
                    __nv_bfloat16 e;
                    e = __float2bfloat16_rn(v00); oh[t1] = e;
                    ol[t1] = __float2bfloat16_rn(v00 - __bfloat162float(e));
                    e = __float2bfloat16_rn(v01); oh[t1 + SEQ] = e;
                    ol[t1 + SEQ] = __float2bfloat16_rn(v01 - __bfloat162float(e));
                    e = __float2bfloat16_rn(v10); oh[t2] = e;
                    ol[t2] = __float2bfloat16_rn(v10 - __bfloat162float(e));
                    e = __float2bfloat16_rn(v11); oh[t2 + SEQ] = e;
                    ol[t2 + SEQ] = __float2bfloat16_rn(v11 - __bfloat162float(e));
                }
            }
        }
    }
}

__global__ __launch_bounds__(256, 1)
void proj_qkv(const __nv_bfloat16* __restrict__ xh, const __nv_bfloat16* __restrict__ xl,
              const __nv_bfloat16* __restrict__ wh, const __nv_bfloat16* __restrict__ wl,
              const float* __restrict__ bq, const float* __restrict__ bk,
              const float* __restrict__ bv,
              __nv_bfloat16* qh, __nv_bfloat16* ql, __nv_bfloat16* kh, __nv_bfloat16* kl,
              __nv_bfloat16* vh, __nv_bfloat16* vl, float qscale)
{
    extern __shared__ __align__(128) char smc[];
    const int z = blockIdx.z;
    const size_t NXo = (size_t)MROWS * DIM;
    const size_t NWo = (size_t)DIM * DIM;
    const __nv_bfloat16* Xh = xh + (size_t)z * NXo;
    const __nv_bfloat16* Xl = xl + (size_t)z * NXo;
    const __nv_bfloat16* Wh = wh + (size_t)z * NWo;
    const __nv_bfloat16* Wl = wl + (size_t)z * NWo;
    const float* bias = (z == 0) ? bq : (z == 1) ? bk : bv;
    void* oA = (z == 0) ? (void*)qh : (z == 1) ? (void*)kh : (void*)vh;
    void* oB = (z == 0) ? (void*)ql : (z == 1) ? (void*)kl : (void*)vl;
    const int mode = (z == 2) ? 2 : 1;
    const float scale = (z == 0) ? qscale : 1.0f;
    proj_body(Xh, Xl, Wh, Wl, bias, oA, oB, mode, scale, smc);
}

__global__ __launch_bounds__(256, 1)
void proj_out(const __nv_bfloat16* __restrict__ Xh, const __nv_bfloat16* __restrict__ Xl,
              const __nv_bfloat16* __restrict__ Wh, const __nv_bfloat16* __restrict__ Wl,
              const float* __restrict__ bias, float* out)
{
    extern __shared__ __align__(128) char smc[];
    proj_body(Xh, Xl, Wh, Wl, bias, out, nullptr, 0, 1.0f, smc);
}

// ---------------------------------------------------------------------------
// Attention (R12, best measured): fixed-bias softmax, 3 smem stages, occ 1.
// ---------------------------------------------------------------------------
#define AQ_H 0
#define AQ_L 16384
#define ABUF0 32768
#define ABUF_SZ 32768
#define ATTN_SMEM 131072
#define NCHUNK (SEQ / 64)
#define MBIAS 12.0f

__global__ __launch_bounds__(256, 1)
void attn_mma(const __nv_bfloat16* __restrict__ qh_g, const __nv_bfloat16* __restrict__ ql_g,
              const __nv_bfloat16* __restrict__ kh_g, const __nv_bfloat16* __restrict__ kl_g,
              const __nv_bfloat16* __restrict__ vh_g, const __nv_bfloat16* __restrict__ vl_g,
              __nv_bfloat16* __restrict__ Oh, __nv_bfloat16* __restrict__ Ol)
{
    extern __shared__ __align__(128) char smc[];
    const uint32_t sb = s2u(smc);
    const int tid = threadIdx.x;
    const int wid = tid >> 5;
    const int lane = tid & 31;

    const int qt = blockIdx.x, h = blockIdx.y, b = blockIdx.z;
    const size_t bh = (size_t)(b * NHEAD + h);
    const int q0 = qt * 128;

    // Q group
    {
        const int a = tid >> 7, r = tid & 127;
        const char* src = (const char*)((a == 0 ? qh_g : ql_g) + (bh * SEQ + q0 + r) * HDIM);
        const uint32_t dst = sb + (a == 0 ? AQ_H : AQ_L) + (uint32_t)r * 128u;
        const uint32_t swz = ((uint32_t)r & 7u) << 4;
#pragma unroll
        for (int i = 0; i < 8; i++)
            CP16(dst + ((uint32_t)(i * 16) ^ swz), src + i * 16);
        CP_COMMIT();
    }

    const int ca = tid >> 6, cr = tid & 63;
    const char* csrc0;
    {
        const __nv_bfloat16* gp;
        size_t off;
        if (ca == 0) { gp = kh_g; off = (bh * SEQ + cr) * HDIM; }
        else if (ca == 1) { gp = kl_g; off = (bh * SEQ + cr) * HDIM; }
        else if (ca == 2) { gp = vh_g; off = (bh * HDIM + cr) * SEQ; }
        else { gp = vl_g; off = (bh * HDIM + cr) * SEQ; }
        csrc0 = (const char*)(gp + off);
    }
    const size_t cstep = (ca < 2) ? (size_t)64 * HDIM * 2 : (size_t)64 * 2;
    const uint32_t cdst0 = sb + ABUF0 + (uint32_t)ca * 8192u + (uint32_t)cr * 128u;
    const uint32_t cswz = ((uint32_t)cr & 7u) << 4;

    // chunks 0,1
#pragma unroll
    for (int s = 0; s < 2; s++) {
        const char* src = csrc0 + (size_t)s * cstep;
        const uint32_t dst = cdst0 + (uint32_t)(s * ABUF_SZ);
#pragma unroll
        for (int i = 0; i < 8; i++)
            CP16(dst + ((uint32_t)(i * 16) ^ cswz), src + i * 16);
        CP_COMMIT();
    }

    CP_WAIT(2);   // Q done (chunks 0,1 may be outstanding)
    __syncthreads();

    const int arow = wid * 16 + (lane & 7) + ((lane >> 3) & 1) * 8;
    const uint32_t aswz = ((uint32_t)lane & 7u) << 4;
    uint32_t qfh[4][4], qfl[4][4];
#pragma unroll
    for (int kt = 0; kt < 4; kt++) {
        const uint32_t cb = (uint32_t)(kt * 32 + (lane >> 4) * 16);
        const uint32_t ad = (uint32_t)arow * 128u + (cb ^ aswz);
        LDSM4(qfh[kt][0], qfh[kt][1], qfh[kt][2], qfh[kt][3], sb + AQ_H + ad);
        LDSM4(qfl[kt][0], qfl[kt][1], qfl[kt][2], qfl[kt][3], sb + AQ_L + ad);
    }

    const int brow = (lane & 7) + (lane >> 4) * 8;
    const uint32_t bswz = ((uint32_t)lane & 7u) << 4;
    const uint32_t bcbs = (uint32_t)(((lane >> 3) & 1) * 16);

    float oacc[8][4];
#pragma unroll
    for (int t = 0; t < 8; t++)
#pragma unroll
        for (int j = 0; j < 4; j++) oacc[t][j] = 0.f;
    float l1 = 0.f, l2 = 0.f;

    int stg = 0;
    for (int c = 0; c < NCHUNK; c++) {
        if (c == NCHUNK - 1) { CP_WAIT(0); } else { CP_WAIT(1); }
        __syncthreads();

        const uint32_t kb_h = sb + ABUF0 + (uint32_t)(stg * ABUF_SZ);
        const uint32_t kb_l = kb_h + 8192u;
        const uint32_t vb_h = kb_h + 16384u;
        const uint32_t vb_l = kb_h + 24576u;

        // ---- S = Q K^T ----
        float sc[8][4];
#pragma unroll
        for (int t = 0; t < 8; t++)
#pragma unroll
            for (int j = 0; j < 4; j++) sc[t][j] = 0.f;

#pragma unroll
        for (int kt = 0; kt < 4; kt++) {
            uint32_t kfh[4][4], kfl[4][4];
#pragma unroll
            for (int u = 0; u < 4; u++) {
                const uint32_t ad = (uint32_t)(16 * u + brow) * 128u +
                                    (((uint32_t)(kt * 32) + bcbs) ^ bswz);
                LDSM4(kfh[u][0], kfh[u][1], kfh[u][2], kfh[u][3], kb_h + ad);
                LDSM4(kfl[u][0], kfl[u][1], kfl[u][2], kfl[u][3], kb_l + ad);
            }
#pragma unroll
            for (int nt = 0; nt < 8; nt++) {
                const int u = nt >> 1, h2 = (nt & 1) * 2;
                MMA16816(sc[nt], qfh[kt][0], qfh[kt][1], qfh[kt][2], qfh[kt][3],
                         kfh[u][h2], kfh[u][h2 + 1]);
                MMA16816(sc[nt], qfh[kt][0], qfh[kt][1], qfh[kt][2], qfh[kt][3],
                         kfl[u][h2], kfl[u][h2 + 1]);
                MMA16816(sc[nt], qfl[kt][0], qfl[kt][1], qfl[kt][2], qfl[kt][3],
                         kfh[u][h2], kfh[u][h2 + 1]);
            }
        }

        // prefetch chunk c+2 (covered by softmax + PV)
        if (c + 2 < NCHUNK) {
            const char* src = csrc0 + (size_t)(c + 2) * cstep;
            int s2i = stg + 2;
            if (s2i >= 3) s2i -= 3;
            const uint32_t dst = cdst0 + (uint32_t)(s2i * ABUF_SZ);
#pragma unroll
            for (int i = 0; i < 8; i++)
                CP16(dst + ((uint32_t)(i * 16) ^ cswz), src + i * 16);
            CP_COMMIT();
        }

        // ---- fixed-bias softmax: P = 2^(S - MBIAS), no reductions ----
#pragma unroll
        for (int t = 0; t < 8; t++) {
            sc[t][0] = ex2f(sc[t][0] - MBIAS);
            sc[t][1] = ex2f(sc[t][1] - MBIAS);
            sc[t][2] = ex2f(sc[t][2] - MBIAS);
            sc[t][3] = ex2f(sc[t][3] - MBIAS);
            l1 += sc[t][0] + sc[t][1];
            l2 += sc[t][2] + sc[t][3];
        }

        // ---- O += P V ----
#pragma unroll
        for (int kt = 0; kt < 4; kt++) {
            uint32_t ph[4], pl[4];
            splitP(sc[2 * kt][0], sc[2 * kt][1], ph[0], pl[0]);
            splitP(sc[2 * kt][2], sc[2 * kt][3], ph[1], pl[1]);
            splitP(sc[2 * kt + 1][0], sc[2 * kt + 1][1], ph[2], pl[2]);
            splitP(sc[2 * kt + 1][2], sc[2 * kt + 1][3], ph[3], pl[3]);

            uint32_t vfh[4][4], vfl[4][4];
#pragma unroll
            for (int u = 0; u < 4; u++) {
                const uint32_t ad = (uint32_t)(16 * u + brow) * 128u +
                                    (((uint32_t)(kt * 32) + bcbs) ^ bswz);
                LDSM4(vfh[u][0], vfh[u][1], vfh[u][2], vfh[u][3], vb_h + ad);
                LDSM4(vfl[u][0], vfl[u][1], vfl[u][2], vfl[u][3], vb_l + ad);
            }
#pragma unroll
            for (int nt = 0; nt < 8; nt++) {
                const int u = nt >> 1, h2 = (nt & 1) * 2;
                MMA16816(oacc[nt], ph[0], ph[1], ph[2], ph[3],
                         vfh[u][h2], vfh[u][h2 + 1]);
                MMA16816(oacc[nt], ph[0], ph[1], ph[2], ph[3],
                         vfl[u][h2], vfl[u][h2 + 1]);
                MMA16816(oacc[nt], pl[0], pl[1], pl[2], pl[3],
                         vfh[u][h2], vfh[u][h2 + 1]);
            }
        }

        stg++;
        if (stg == 3) stg = 0;
    }

    l1 += __shfl_xor_sync(0xffffffffu, l1, 1);
    l1 += __shfl_xor_sync(0xffffffffu, l1, 2);
    l2 += __shfl_xor_sync(0xffffffffu, l2, 1);
    l2 += __shfl_xor_sync(0xffffffffu, l2, 2);
    const float inv1 = 1.f / l1, inv2 = 1.f / l2;

    const int r1 = q0 + wid * 16 + (lane >> 2);
    const size_t i1 = ((size_t)b * SEQ + r1) * DIM + h * HDIM + (lane & 3) * 2;
    const size_t i2 = i1 + (size_t)8 * DIM;
#pragma unroll
    for (int t = 0; t < 8; t++) {
        uint32_t hh, ll;
        split2(oacc[t][0] * inv1, oacc[t][1] * inv1, hh, ll);
        *(uint32_t*)(Oh + i1 + t * 8) = hh;
        *(uint32_t*)(Ol + i1 + t * 8) = ll;
        split2(oacc[t][2] * inv2, oacc[t][3] * inv2, hh, ll);
        *(uint32_t*)(Oh + i2 + t * 8) = hh;
        *(uint32_t*)(Ol + i2 + t * 8) = ll;
    }
}

// ---------------------------------------------------------------------------
extern "C" void kernel_launch(void* const* d_in, const int* in_sizes, int n_in,
                              void* d_out, int out_size)
{
    const float* query = (const float*)d_in[0];
    const float* key   = (const float*)d_in[1];
    const float* value = (const float*)d_in[2];
    const float* Wq = (const float*)d_in[3];
    const float* bq = (const float*)d_in[4];
    const float* Wk = (const float*)d_in[5];
    const float* bk = (const float*)d_in[6];
    const float* Wv = (const float*)d_in[7];
    const float* bv = (const float*)d_in[8];
    const float* Wo = (const float*)d_in[9];
    const float* bo = (const float*)d_in[10];
    float* out = (float*)d_out;

    __nv_bfloat16 *xh, *xl, *wh, *wl;
    __nv_bfloat16 *qh, *ql, *kh, *kl, *vh, *vl, *ath, *atl;
    cudaGetSymbolAddress((void**)&xh, g_xh);
    cudaGetSymbolAddress((void**)&xl, g_xl);
    cudaGetSymbolAddress((void**)&wh, g_wh);
    cudaGetSymbolAddress((void**)&wl, g_wl);
    cudaGetSymbolAddress((void**)&qh, g_qh);
    cudaGetSymbolAddress((void**)&ql, g_ql);
    cudaGetSymbolAddress((void**)&kh, g_kh);
    cudaGetSymbolAddress((void**)&kl, g_kl);
    cudaGetSymbolAddress((void**)&vh, g_vh);
    cudaGetSymbolAddress((void**)&vl, g_vl);
    cudaGetSymbolAddress((void**)&ath, g_ath);
    cudaGetSymbolAddress((void**)&atl, g_atl);

    cudaFuncSetAttribute(proj_qkv, cudaFuncAttributeMaxDynamicSharedMemorySize, PROJ_SMEM);
    cudaFuncSetAttribute(proj_out, cudaFuncAttributeMaxDynamicSharedMemorySize, PROJ_SMEM);
    cudaFuncSetAttribute(attn_mma, cudaFuncAttributeMaxDynamicSharedMemorySize, ATTN_SMEM);

    const int NX = MROWS * DIM;
    const int NW = DIM * DIM;
    {
        dim3 gx(2048, 3);
        split_many<<<gx, 256>>>((const float4*)query, (const float4*)key,
                                (const float4*)value, (const float4*)value,
                                (uint2*)xh, (uint2*)xl, NX / 4);
        dim3 gw(512, 4);
        split_many<<<gw, 256>>>((const float4*)Wq, (const float4*)Wk,
                                (const float4*)Wv, (const float4*)Wo,
                                (uint2*)wh, (uint2*)wl, NW / 4);
    }

    const float QSCALE = 0.125f * 1.44269504f;
    dim3 pg3(DIM / 128, MROWS / 128, 3);
    proj_qkv<<<pg3, 256, PROJ_SMEM>>>(xh, xl, wh, wl, bq, bk, bv,
                                      qh, ql, kh, kl, vh, vl, QSCALE);

    dim3 ag(SEQ / 128, NHEAD, BBATCH);
    attn_mma<<<ag, 256, ATTN_SMEM>>>(qh, ql, kh, kl, vh, vl, ath, atl);

    dim3 pg(DIM / 128, MROWS / 128);
    proj_out<<<pg, 256, PROJ_SMEM>>>(ath, atl, wh + (size_t)3 * NW, wl + (size_t)3 * NW,
                                     bo, out);
}

// round 15
// speedup vs baseline: 1.1252x; 1.1252x over previous
#include <cuda_runtime.h>
#include <cuda_bf16.h>
#include <stdint.h>

#define BBATCH 4
#define SEQ 2048
#define DIM 1024
#define NHEAD 16
#define HDIM 64
#define MROWS (BBATCH * SEQ)   // 8192

__device__ __nv_bfloat16 g_xh[3][MROWS * DIM];
__device__ __nv_bfloat16 g_xl[3][MROWS * DIM];
__device__ __nv_bfloat16 g_wh[4][DIM * DIM];
__device__ __nv_bfloat16 g_wl[4][DIM * DIM];
__device__ __nv_bfloat16 g_qh[BBATCH * NHEAD * SEQ * HDIM];  // [B,H,S,HD]
__device__ __nv_bfloat16 g_ql[BBATCH * NHEAD * SEQ * HDIM];
__device__ __nv_bfloat16 g_kh[BBATCH * NHEAD * SEQ * HDIM];
__device__ __nv_bfloat16 g_kl[BBATCH * NHEAD * SEQ * HDIM];
__device__ __nv_bfloat16 g_vh[BBATCH * NHEAD * SEQ * HDIM];  // [B,H,S,HD] (coalesced)
__device__ __nv_bfloat16 g_vl[BBATCH * NHEAD * SEQ * HDIM];
__device__ __nv_bfloat16 g_ath[BBATCH * SEQ * DIM];
__device__ __nv_bfloat16 g_atl[BBATCH * SEQ * DIM];

// ---------------------------------------------------------------------------
__device__ __forceinline__ uint32_t s2u(const void* p) {
    uint32_t a;
    asm("{ .reg .u64 t; cvta.to.shared.u64 t, %1; cvt.u32.u64 %0, t; }" : "=r"(a) : "l"(p));
    return a;
}
__device__ __forceinline__ float ex2f(float x) {
    float y;
    asm("ex2.approx.f32 %0, %1;" : "=f"(y) : "f"(x));
    return y;
}

#define LDSM4(r0, r1, r2, r3, a) \
    asm volatile("ldmatrix.sync.aligned.m8n8.x4.shared.b16 {%0,%1,%2,%3}, [%4];" \
                 : "=r"(r0), "=r"(r1), "=r"(r2), "=r"(r3) : "r"(a))

#define LDSM4T(r0, r1, r2, r3, a) \
    asm volatile("ldmatrix.sync.aligned.m8n8.x4.trans.shared.b16 {%0,%1,%2,%3}, [%4];" \
                 : "=r"(r0), "=r"(r1), "=r"(r2), "=r"(r3) : "r"(a))

#define MMA16816(d, a0, a1, a2, a3, b0, b1) \
    asm volatile("mma.sync.aligned.m16n8k16.row.col.f32.bf16.bf16.f32 " \
                 "{%0,%1,%2,%3},{%4,%5,%6,%7},{%8,%9},{%0,%1,%2,%3};" \
                 : "+f"((d)[0]), "+f"((d)[1]), "+f"((d)[2]), "+f"((d)[3]) \
                 : "r"(a0), "r"(a1), "r"(a2), "r"(a3), "r"(b0), "r"(b1))

#define CP16(d, s) \
    asm volatile("cp.async.cg.shared.global [%0], [%1], 16;" :: "r"(d), "l"(s))
#define CP_COMMIT() asm volatile("cp.async.commit_group;" ::: "memory")
#define CP_WAIT(n)  asm volatile("cp.async.wait_group %0;" :: "n"(n) : "memory")

__device__ __forceinline__ void split2(float a, float b, uint32_t& h, uint32_t& l) {
    __nv_bfloat16 ha = __float2bfloat16_rn(a);
    __nv_bfloat16 hb = __float2bfloat16_rn(b);
    float la = a - __bfloat162float(ha);
    float lb = b - __bfloat162float(hb);
    __nv_bfloat162 H = __halves2bfloat162(ha, hb);
    __nv_bfloat162 L = __floats2bfloat162_rn(la, lb);
    h = *reinterpret_cast<uint32_t*>(&H);
    l = *reinterpret_cast<uint32_t*>(&L);
}
__device__ __forceinline__ void splitP(float a, float b, uint32_t& h, uint32_t& l) {
    const uint32_t ua = __float_as_uint(a), ub = __float_as_uint(b);
    h = __byte_perm(ua, ub, 0x7632);
    const float la = a - __uint_as_float(ua & 0xFFFF0000u);
    const float lb = b - __uint_as_float(ub & 0xFFFF0000u);
    __nv_bfloat162 L = __floats2bfloat162_rn(la, lb);
    l = *reinterpret_cast<uint32_t*>(&L);
}

// ---------------------------------------------------------------------------
__global__ __launch_bounds__(256)
void split_many(const float4* __restrict__ x0, const float4* __restrict__ x1,
                const float4* __restrict__ x2, const float4* __restrict__ x3,
                uint2* __restrict__ hb, uint2* __restrict__ lb, int n4)
{
    const int t = blockIdx.y;
    const float4* x = (t == 0) ? x0 : (t == 1) ? x1 : (t == 2) ? x2 : x3;
    uint2* h = hb + (size_t)t * n4;
    uint2* l = lb + (size_t)t * n4;
    for (int i = blockIdx.x * 256 + threadIdx.x; i < n4; i += gridDim.x * 256) {
        float4 v = x[i];
        uint2 hi, lo;
        split2(v.x, v.y, hi.x, lo.x);
        split2(v.z, v.w, hi.y, lo.y);
        h[i] = hi;
        l[i] = lo;
    }
}

// ---------------------------------------------------------------------------
// Split-bf16 GEMM body (R12 structure: BK=32, 3-stage cp.async, 96KB, occ 2).
// mode 0: fp32 [M,N]; mode 1: split bf16 [B,H,S,HD] (coalesced).
// ---------------------------------------------------------------------------
#define PROJ_STG 32768
#define PROJ_SMEM 98304
#define NIT 32

__device__ __forceinline__ void proj_body(
    const __nv_bfloat16* __restrict__ Xh, const __nv_bfloat16* __restrict__ Xl,
    const __nv_bfloat16* __restrict__ Wh, const __nv_bfloat16* __restrict__ Wl,
    const float* __restrict__ bias, void* outA, void* outB,
    int mode, float scale, char* smc)
{
    const uint32_t sb = s2u(smc);
    const int tid = threadIdx.x;
    const int wid = tid >> 5;
    const int lane = tid & 31;

    const int m0 = blockIdx.y * 128;
    const int n0 = blockIdx.x * 128;
    const int wm = wid & 1;
    const int wn = wid >> 1;

    const int la_ = tid >> 6;
    const int pr = tid & 63;
    const __nv_bfloat16* gp = (la_ == 0) ? Xh : (la_ == 1) ? Xl : (la_ == 2) ? Wh : Wl;
    const int rb = (la_ < 2) ? m0 : n0;
    const char* gsrc = (const char*)(gp + (size_t)(rb + pr * 2) * DIM);
    const uint32_t ld0 = sb + (uint32_t)la_ * 8192u + (uint32_t)(pr * 2) * 64u;
    const uint32_t swr = ((uint32_t)pr & 3u) << 4;

    const int a_rin = (lane & 7) + ((lane >> 3) & 1) * 8;
    const uint32_t a_cbs = (uint32_t)((lane >> 4) * 16);
    const int b_rin = (lane & 7) + (lane >> 4) * 8;
    const uint32_t b_cbs = (uint32_t)(((lane >> 3) & 1) * 16);

    uint32_t aoff[4], arx[4];
#pragma unroll
    for (int t = 0; t < 4; t++) {
        const uint32_t r = (uint32_t)(wm * 64 + t * 16 + a_rin);
        aoff[t] = r * 64u;
        arx[t] = ((r >> 1) & 3u) << 4;
    }
    uint32_t boff[2], brx[2];
#pragma unroll
    for (int u = 0; u < 2; u++) {
        const uint32_t r = (uint32_t)(wn * 32 + u * 16 + b_rin);
        boff[u] = r * 64u;
        brx[u] = ((r >> 1) & 3u) << 4;
    }

    float acc[4][4][4];
#pragma unroll
    for (int i = 0; i < 4; i++)
#pragma unroll
        for (int j = 0; j < 4; j++)
#pragma unroll
            for (int c = 0; c < 4; c++) acc[i][j][c] = 0.f;

#pragma unroll
    for (int s = 0; s < 2; s++) {
        const char* s0 = gsrc + s * 64;
        const char* s1 = s0 + DIM * 2;
        const uint32_t d = ld0 + (uint32_t)(s * PROJ_STG);
#pragma unroll
        for (int i = 0; i < 4; i++) CP16(d + (((uint32_t)(i * 16)) ^ swr), s0 + i * 16);
#pragma unroll
        for (int i = 0; i < 4; i++) CP16(d + 64u + (((uint32_t)(i * 16)) ^ swr), s1 + i * 16);
        CP_COMMIT();
    }

    int stg = 0;
    for (int it = 0; it < NIT; it++) {
        if (it == NIT - 1) { CP_WAIT(0); } else { CP_WAIT(1); }
        __syncthreads();

        const uint32_t st = sb + (uint32_t)(stg * PROJ_STG);
        const uint32_t sAh = st, sAl = st + 8192u, sBh = st + 16384u, sBl = st + 24576u;

        uint32_t bh[2][4], bl[2][4], ah[4][4], al[4][4];
#pragma unroll
        for (int u = 0; u < 2; u++) {
            const uint32_t ad = boff[u] + (b_cbs ^ brx[u]);
            LDSM4(bh[u][0], bh[u][1], bh[u][2], bh[u][3], sBh + ad);
            LDSM4(bl[u][0], bl[u][1], bl[u][2], bl[u][3], sBl + ad);
        }
#pragma unroll
        for (int t = 0; t < 4; t++) {
            const uint32_t ad = aoff[t] + (a_cbs ^ arx[t]);
            LDSM4(ah[t][0], ah[t][1], ah[t][2], ah[t][3], sAh + ad);
            LDSM4(al[t][0], al[t][1], al[t][2], al[t][3], sAl + ad);
        }

        if (it + 2 < NIT) {
            const char* s0 = gsrc + (it + 2) * 64;
            const char* s1 = s0 + DIM * 2;
            const uint32_t d = ld0 + (uint32_t)(((it + 2) % 3) * PROJ_STG);
#pragma unroll
            for (int i = 0; i < 4; i++) CP16(d + (((uint32_t)(i * 16)) ^ swr), s0 + i * 16);
#pragma unroll
            for (int i = 0; i < 4; i++) CP16(d + 64u + (((uint32_t)(i * 16)) ^ swr), s1 + i * 16);
            CP_COMMIT();
        }

#pragma unroll
        for (int t = 0; t < 4; t++)
#pragma unroll
            for (int nt = 0; nt < 4; nt++) {
                const int u = nt >> 1, h2 = (nt & 1) * 2;
                MMA16816(acc[t][nt], ah[t][0], ah[t][1], ah[t][2], ah[t][3],
                         bh[u][h2], bh[u][h2 + 1]);
                MMA16816(acc[t][nt], ah[t][0], ah[t][1], ah[t][2], ah[t][3],
                         bl[u][h2], bl[u][h2 + 1]);
                MMA16816(acc[t][nt], al[t][0], al[t][1], al[t][2], al[t][3],
                         bh[u][h2], bh[u][h2 + 1]);
            }

#pragma unroll
        for (int u = 0; u < 2; u++) {
            const uint32_t ad = boff[u] + (((uint32_t)32 + b_cbs) ^ brx[u]);
            LDSM4(bh[u][0], bh[u][1], bh[u][2], bh[u][3], sBh + ad);
            LDSM4(bl[u][0], bl[u][1], bl[u][2], bl[u][3], sBl + ad);
        }
#pragma unroll
        for (int t = 0; t < 4; t++) {
            const uint32_t ad = aoff[t] + (((uint32_t)32 + a_cbs) ^ arx[t]);
            LDSM4(ah[t][0], ah[t][1], ah[t][2], ah[t][3], sAh + ad);
            LDSM4(al[t][0], al[t][1], al[t][2], al[t][3], sAl + ad);
        }
#pragma unroll
        for (int t = 0; t < 4; t++)
#pragma unroll
            for (int nt = 0; nt < 4; nt++) {
                const int u = nt >> 1, h2 = (nt & 1) * 2;
                MMA16816(acc[t][nt], ah[t][0], ah[t][1], ah[t][2], ah[t][3],
                         bh[u][h2], bh[u][h2 + 1]);
                MMA16816(acc[t][nt], ah[t][0], ah[t][1], ah[t][2], ah[t][3],
                         bl[u][h2], bl[u][h2 + 1]);
                MMA16816(acc[t][nt], al[t][0], al[t][1], al[t][2], al[t][3],
                         bh[u][h2], bh[u][h2 + 1]);
            }

        stg++;
        if (stg == 3) stg = 0;
    }

#pragma unroll
    for (int mt = 0; mt < 4; mt++) {
        const int m1 = m0 + wm * 64 + mt * 16 + (lane >> 2);
        const int m2 = m1 + 8;
#pragma unroll
        for (int nt = 0; nt < 4; nt++) {
            const int n = n0 + wn * 32 + nt * 8 + (lane & 3) * 2;
            const float b0v = bias[n], b1v = bias[n + 1];
            const float v00 = (acc[mt][nt][0] + b0v) * scale;
            const float v01 = (acc[mt][nt][1] + b1v) * scale;
            const float v10 = (acc[mt][nt][2] + b0v) * scale;
            const float v11 = (acc[mt][nt][3] + b1v) * scale;
            if (mode == 0) {
                float* out = (float*)outA;
                *(float2*)(out + (size_t)m1 * DIM + n) = make_float2(v00, v01);
                *(float2*)(out + (size_t)m2 * DIM + n) = make_float2(v10, v11);
            } else {
                const int h = n >> 6, hd = n & 63;
                const int b1i = m1 >> 11, s1 = m1 & 2047;
                const int b2i = m2 >> 11, s2 = m2 & 2047;
                __nv_bfloat16* oh = (__nv_bfloat16*)outA;
                __nv_bfloat16* ol = (__nv_bfloat16*)outB;
                uint32_t h0, l0, h1, l1;
                split2(v00, v01, h0, l0);
                split2(v10, v11, h1, l1);
                const size_t i1 = (((size_t)b1i * NHEAD + h) * SEQ + s1) * HDIM + hd;
                const size_t i2 = (((size_t)b2i * NHEAD + h) * SEQ + s2) * HDIM + hd;
                *(uint32_t*)(oh + i1) = h0;
                *(uint32_t*)(ol + i1) = l0;
                *(uint32_t*)(oh + i2) = h1;
                *(uint32_t*)(ol + i2) = l1;
            }
        }
    }
}

__global__ __launch_bounds__(256, 2)
void proj_qkv(const __nv_bfloat16* __restrict__ xh, const __nv_bfloat16* __restrict__ xl,
              const __nv_bfloat16* __restrict__ wh, const __nv_bfloat16* __restrict__ wl,
              const float* __restrict__ bq, const float* __restrict__ bk,
              const float* __restrict__ bv,
              __nv_bfloat16* qh, __nv_bfloat16* ql, __nv_bfloat16* kh, __nv_bfloat16* kl,
              __nv_bfloat16* vh, __nv_bfloat16* vl, float qscale)
{
    extern __shared__ __align__(128) char smc[];
    const int z = blockIdx.z;
    const size_t NXo = (size_t)MROWS * DIM;
    const size_t NWo = (size_t)DIM * DIM;
    const __nv_bfloat16* Xh = xh + (size_t)z * NXo;
    const __nv_bfloat16* Xl = xl + (size_t)z * NXo;
    const __nv_bfloat16* Wh = wh + (size_t)z * NWo;
    const __nv_bfloat16* Wl = wl + (size_t)z * NWo;
    const float* bias = (z == 0) ? bq : (z == 1) ? bk : bv;
    void* oA = (z == 0) ? (void*)qh : (z == 1) ? (void*)kh : (void*)vh;
    void* oB = (z == 0) ? (void*)ql : (z == 1) ? (void*)kl : (void*)vl;
    const float scale = (z == 0) ? qscale : 1.0f;
    proj_body(Xh, Xl, Wh, Wl, bias, oA, oB, 1, scale, smc);
}

__global__ __launch_bounds__(256, 2)
void proj_out(const __nv_bfloat16* __restrict__ Xh, const __nv_bfloat16* __restrict__ Xl,
              const __nv_bfloat16* __restrict__ Wh, const __nv_bfloat16* __restrict__ Wl,
              const float* __restrict__ bias, float* out)
{
    extern __shared__ __align__(128) char smc[];
    proj_body(Xh, Xl, Wh, Wl, bias, out, nullptr, 0, 1.0f, smc);
}

// ---------------------------------------------------------------------------
// Attention (R12 structure): fixed-bias softmax, 3 smem stages, occ 1.
// V now stored [B,H,S,HD] like K; PV uses ldmatrix.trans for B fragments.
// ---------------------------------------------------------------------------
#define AQ_H 0
#define AQ_L 16384
#define ABUF0 32768
#define ABUF_SZ 32768
#define ATTN_SMEM 131072
#define NCHUNK (SEQ / 64)
#define MBIAS 12.0f

__global__ __launch_bounds__(256, 1)
void attn_mma(const __nv_bfloat16* __restrict__ qh_g, const __nv_bfloat16* __restrict__ ql_g,
              const __nv_bfloat16* __restrict__ kh_g, const __nv_bfloat16* __restrict__ kl_g,
              const __nv_bfloat16* __restrict__ vh_g, const __nv_bfloat16* __restrict__ vl_g,
              __nv_bfloat16* __restrict__ Oh, __nv_bfloat16* __restrict__ Ol)
{
    extern __shared__ __align__(128) char smc[];
    const uint32_t sb = s2u(smc);
    const int tid = threadIdx.x;
    const int wid = tid >> 5;
    const int lane = tid & 31;

    const int qt = blockIdx.x, h = blockIdx.y, b = blockIdx.z;
    const size_t bh = (size_t)(b * NHEAD + h);
    const int q0 = qt * 128;

    // Q group
    {
        const int a = tid >> 7, r = tid & 127;
        const char* src = (const char*)((a == 0 ? qh_g : ql_g) + (bh * SEQ + q0 + r) * HDIM);
        const uint32_t dst = sb + (a == 0 ? AQ_H : AQ_L) + (uint32_t)r * 128u;
        const uint32_t swz = ((uint32_t)r & 7u) << 4;
#pragma unroll
        for (int i = 0; i < 8; i++)
            CP16(dst + ((uint32_t)(i * 16) ^ swz), src + i * 16);
        CP_COMMIT();
    }

    // chunk loader: all four arrays share the [B,H,S,HD] layout now
    const int ca = tid >> 6, cr = tid & 63;
    const __nv_bfloat16* gpc = (ca == 0) ? kh_g : (ca == 1) ? kl_g : (ca == 2) ? vh_g : vl_g;
    const char* csrc0 = (const char*)(gpc + (bh * SEQ + cr) * HDIM);
    const size_t cstep = (size_t)64 * HDIM * 2;
    const uint32_t cdst0 = sb + ABUF0 + (uint32_t)ca * 8192u + (uint32_t)cr * 128u;
    const uint32_t cswz = ((uint32_t)cr & 7u) << 4;

    // chunks 0,1
#pragma unroll
    for (int s = 0; s < 2; s++) {
        const char* src = csrc0 + (size_t)s * cstep;
        const uint32_t dst = cdst0 + (uint32_t)(s * ABUF_SZ);
#pragma unroll
        for (int i = 0; i < 8; i++)
            CP16(dst + ((uint32_t)(i * 16) ^ cswz), src + i * 16);
        CP_COMMIT();
    }

    CP_WAIT(2);   // Q done (chunks 0,1 may be outstanding)
    __syncthreads();

    const int arow = wid * 16 + (lane & 7) + ((lane >> 3) & 1) * 8;
    const uint32_t aswz = ((uint32_t)lane & 7u) << 4;
    uint32_t qfh[4][4], qfl[4][4];
#pragma unroll
    for (int kt = 0; kt < 4; kt++) {
        const uint32_t cb = (uint32_t)(kt * 32 + (lane >> 4) * 16);
        const uint32_t ad = (uint32_t)arow * 128u + (cb ^ aswz);
        LDSM4(qfh[kt][0], qfh[kt][1], qfh[kt][2], qfh[kt][3], sb + AQ_H + ad);
        LDSM4(qfl[kt][0], qfl[kt][1], qfl[kt][2], qfl[kt][3], sb + AQ_L + ad);
    }

    const int brow = (lane & 7) + (lane >> 4) * 8;
    const uint32_t bswz = ((uint32_t)lane & 7u) << 4;
    const uint32_t bcbs = (uint32_t)(((lane >> 3) & 1) * 16);

    // V trans-ldmatrix geometry: rows = key = kt*16 + (lane&15),
    // colbyte = u*32 + (lane>>4)*16; swizzle = (lane&7)<<4 (row&7 == lane&7).
    const uint32_t vrow_in = (uint32_t)(lane & 15);
    const uint32_t vcb = (uint32_t)((lane >> 4) * 16);

    float oacc[8][4];
#pragma unroll
    for (int t = 0; t < 8; t++)
#pragma unroll
        for (int j = 0; j < 4; j++) oacc[t][j] = 0.f;
    float l1 = 0.f, l2 = 0.f;

    int stg = 0;
    for (int c = 0; c < NCHUNK; c++) {
        if (c == NCHUNK - 1) { CP_WAIT(0); } else { CP_WAIT(1); }
        __syncthreads();

        const uint32_t kb_h = sb + ABUF0 + (uint32_t)(stg * ABUF_SZ);
        const uint32_t kb_l = kb_h + 8192u;
        const uint32_t vb_h = kb_h + 16384u;
        const uint32_t vb_l = kb_h + 24576u;

        // ---- S = Q K^T ----
        float sc[8][4];
#pragma unroll
        for (int t = 0; t < 8; t++)
#pragma unroll
            for (int j = 0; j < 4; j++) sc[t][j] = 0.f;

#pragma unroll
        for (int kt = 0; kt < 4; kt++) {
            uint32_t kfh[4][4], kfl[4][4];
#pragma unroll
            for (int u = 0; u < 4; u++) {
                const uint32_t ad = (uint32_t)(16 * u + brow) * 128u +
                                    (((uint32_t)(kt * 32) + bcbs) ^ bswz);
                LDSM4(kfh[u][0], kfh[u][1], kfh[u][2], kfh[u][3], kb_h + ad);
                LDSM4(kfl[u][0], kfl[u][1], kfl[u][2], kfl[u][3], kb_l + ad);
            }
#pragma unroll
            for (int nt = 0; nt < 8; nt++) {
                const int u = nt >> 1, h2 = (nt & 1) * 2;
                MMA16816(sc[nt], qfh[kt][0], qfh[kt][1], qfh[kt][2], qfh[kt][3],
                         kfh[u][h2], kfh[u][h2 + 1]);
                MMA16816(sc[nt], qfh[kt][0], qfh[kt][1], qfh[kt][2], qfh[kt][3],
                         kfl[u][h2], kfl[u][h2 + 1]);
                MMA16816(sc[nt], qfl[kt][0], qfl[kt][1], qfl[kt][2], qfl[kt][3],
                         kfh[u][h2], kfh[u][h2 + 1]);
            }
        }

        // prefetch chunk c+2 (covered by softmax + PV)
        if (c + 2 < NCHUNK) {
            const char* src = csrc0 + (size_t)(c + 2) * cstep;
            int s2i = stg + 2;
            if (s2i >= 3) s2i -= 3;
            const uint32_t dst = cdst0 + (uint32_t)(s2i * ABUF_SZ);
#pragma unroll
            for (int i = 0; i < 8; i++)
                CP16(dst + ((uint32_t)(i * 16) ^ cswz), src + i * 16);
            CP_COMMIT();
        }

        // ---- fixed-bias softmax: P = 2^(S - MBIAS), no reductions ----
#pragma unroll
        for (int t = 0; t < 8; t++) {
            sc[t][0] = ex2f(sc[t][0] - MBIAS);
            sc[t][1] = ex2f(sc[t][1] - MBIAS);
            sc[t][2] = ex2f(sc[t][2] - MBIAS);
            sc[t][3] = ex2f(sc[t][3] - MBIAS);
            l1 += sc[t][0] + sc[t][1];
            l2 += sc[t][2] + sc[t][3];
        }

        // ---- O += P V (V tile is [key][hd]; trans ldmatrix for B) ----
#pragma unroll
        for (int kt = 0; kt < 4; kt++) {
            uint32_t ph[4], pl[4];
            splitP(sc[2 * kt][0], sc[2 * kt][1], ph[0], pl[0]);
            splitP(sc[2 * kt][2], sc[2 * kt][3], ph[1], pl[1]);
            splitP(sc[2 * kt + 1][0], sc[2 * kt + 1][1], ph[2], pl[2]);
            splitP(sc[2 * kt + 1][2], sc[2 * kt + 1][3], ph[3], pl[3]);

            const uint32_t vrbase = (uint32_t)(kt * 16) + vrow_in;
#pragma unroll
            for (int u = 0; u < 4; u++) {
                uint32_t vh4[4], vl4[4];
                const uint32_t ad = vrbase * 128u +
                                    (((uint32_t)(u * 32) + vcb) ^ bswz);
                LDSM4T(vh4[0], vh4[1], vh4[2], vh4[3], vb_h + ad);
                LDSM4T(vl4[0], vl4[1], vl4[2], vl4[3], vb_l + ad);
                // same per-accumulator order as before: hh, hl, lh
                MMA16816(oacc[2 * u],     ph[0], ph[1], ph[2], ph[3], vh4[0], vh4[1]);
                MMA16816(oacc[2 * u],     ph[0], ph[1], ph[2], ph[3], vl4[0], vl4[1]);
                MMA16816(oacc[2 * u],     pl[0], pl[1], pl[2], pl[3], vh4[0], vh4[1]);
                MMA16816(oacc[2 * u + 1], ph[0], ph[1], ph[2], ph[3], vh4[2], vh4[3]);
                MMA16816(oacc[2 * u + 1], ph[0], ph[1], ph[2], ph[3], vl4[2], vl4[3]);
                MMA16816(oacc[2 * u + 1], pl[0], pl[1], pl[2], pl[3], vh4[2], vh4[3]);
            }
        }

        stg++;
        if (stg == 3) stg = 0;
    }

    l1 += __shfl_xor_sync(0xffffffffu, l1, 1);
    l1 += __shfl_xor_sync(0xffffffffu, l1, 2);
    l2 += __shfl_xor_sync(0xffffffffu, l2, 1);
    l2 += __shfl_xor_sync(0xffffffffu, l2, 2);
    const float inv1 = 1.f / l1, inv2 = 1.f / l2;

    const int r1 = q0 + wid * 16 + (lane >> 2);
    const size_t i1 = ((size_t)b * SEQ + r1) * DIM + h * HDIM + (lane & 3) * 2;
    const size_t i2 = i1 + (size_t)8 * DIM;
#pragma unroll
    for (int t = 0; t < 8; t++) {
        uint32_t hh, ll;
        split2(oacc[t][0] * inv1, oacc[t][1] * inv1, hh, ll);
        *(uint32_t*)(Oh + i1 + t * 8) = hh;
        *(uint32_t*)(Ol + i1 + t * 8) = ll;
        split2(oacc[t][2] * inv2, oacc[t][3] * inv2, hh, ll);
        *(uint32_t*)(Oh + i2 + t * 8) = hh;
        *(uint32_t*)(Ol + i2 + t * 8) = ll;
    }
}

// ---------------------------------------------------------------------------
extern "C" void kernel_launch(void* const* d_in, const int* in_sizes, int n_in,
                              void* d_out, int out_size)
{
    const float* query = (const float*)d_in[0];
    const float* key   = (const float*)d_in[1];
    const float* value = (const float*)d_in[2];
    const float* Wq = (const float*)d_in[3];
    const float* bq = (const float*)d_in[4];
    const float* Wk = (const float*)d_in[5];
    const float* bk = (const float*)d_in[6];
    const float* Wv = (const float*)d_in[7];
    const float* bv = (const float*)d_in[8];
    const float* Wo = (const float*)d_in[9];
    const float* bo = (const float*)d_in[10];
    float* out = (float*)d_out;

    __nv_bfloat16 *xh, *xl, *wh, *wl;
    __nv_bfloat16 *qh, *ql, *kh, *kl, *vh, *vl, *ath, *atl;
    cudaGetSymbolAddress((void**)&xh, g_xh);
    cudaGetSymbolAddress((void**)&xl, g_xl);
    cudaGetSymbolAddress((void**)&wh, g_wh);
    cudaGetSymbolAddress((void**)&wl, g_wl);
    cudaGetSymbolAddress((void**)&qh, g_qh);
    cudaGetSymbolAddress((void**)&ql, g_ql);
    cudaGetSymbolAddress((void**)&kh, g_kh);
    cudaGetSymbolAddress((void**)&kl, g_kl);
    cudaGetSymbolAddress((void**)&vh, g_vh);
    cudaGetSymbolAddress((void**)&vl, g_vl);
    cudaGetSymbolAddress((void**)&ath, g_ath);
    cudaGetSymbolAddress((void**)&atl, g_atl);

    cudaFuncSetAttribute(proj_qkv, cudaFuncAttributeMaxDynamicSharedMemorySize, PROJ_SMEM);
    cudaFuncSetAttribute(proj_out, cudaFuncAttributeMaxDynamicSharedMemorySize, PROJ_SMEM);
    cudaFuncSetAttribute(attn_mma, cudaFuncAttributeMaxDynamicSharedMemorySize, ATTN_SMEM);

    const int NX = MROWS * DIM;
    const int NW = DIM * DIM;
    {
        dim3 gx(2048, 3);
        split_many<<<gx, 256>>>((const float4*)query, (const float4*)key,
                                (const float4*)value, (const float4*)value,
                                (uint2*)xh, (uint2*)xl, NX / 4);
        dim3 gw(512, 4);
        split_many<<<gw, 256>>>((const float4*)Wq, (const float4*)Wk,
                                (const float4*)Wv, (const float4*)Wo,
                                (uint2*)wh, (uint2*)wl, NW / 4);
    }

    const float QSCALE = 0.125f * 1.44269504f;
    dim3 pg3(DIM / 128, MROWS / 128, 3);
    proj_qkv<<<pg3, 256, PROJ_SMEM>>>(xh, xl, wh, wl, bq, bk, bv,
                                      qh, ql, kh, kl, vh, vl, QSCALE);

    dim3 ag(SEQ / 128, NHEAD, BBATCH);
    attn_mma<<<ag, 256, ATTN_SMEM>>>(qh, ql, kh, kl, vh, vl, ath, atl);

    dim3 pg(DIM / 128, MROWS / 128);
    proj_out<<<pg, 256, PROJ_SMEM>>>(ath, atl, wh + (size_t)3 * NW, wl + (size_t)3 * NW,
                                     bo, out);
}

// round 16
// speedup vs baseline: 1.1967x; 1.0635x over previous
#include <cuda_runtime.h>
#include <cuda_bf16.h>
#include <stdint.h>

#define BBATCH 4
#define SEQ 2048
#define DIM 1024
#define NHEAD 16
#define HDIM 64
#define MROWS (BBATCH * SEQ)   // 8192

__device__ __nv_bfloat16 g_xh[3][MROWS * DIM];
__device__ __nv_bfloat16 g_xl[3][MROWS * DIM];
__device__ __nv_bfloat16 g_wh[4][DIM * DIM];
__device__ __nv_bfloat16 g_wl[4][DIM * DIM];
__device__ __nv_bfloat16 g_qh[BBATCH * NHEAD * SEQ * HDIM];  // [B,H,S,HD]
__device__ __nv_bfloat16 g_ql[BBATCH * NHEAD * SEQ * HDIM];
__device__ __nv_bfloat16 g_kh[BBATCH * NHEAD * SEQ * HDIM];
__device__ __nv_bfloat16 g_kl[BBATCH * NHEAD * SEQ * HDIM];
__device__ __nv_bfloat16 g_vh[BBATCH * NHEAD * SEQ * HDIM];  // [B,H,S,HD] (coalesced)
__device__ __nv_bfloat16 g_vl[BBATCH * NHEAD * SEQ * HDIM];
__device__ __nv_bfloat16 g_ath[BBATCH * SEQ * DIM];
__device__ __nv_bfloat16 g_atl[BBATCH * SEQ * DIM];

// ---------------------------------------------------------------------------
__device__ __forceinline__ uint32_t s2u(const void* p) {
    uint32_t a;
    asm("{ .reg .u64 t; cvta.to.shared.u64 t, %1; cvt.u32.u64 %0, t; }" : "=r"(a) : "l"(p));
    return a;
}
__device__ __forceinline__ float ex2f(float x) {
    float y;
    asm("ex2.approx.f32 %0, %1;" : "=f"(y) : "f"(x));
    return y;
}

#define LDSM4(r0, r1, r2, r3, a) \
    asm volatile("ldmatrix.sync.aligned.m8n8.x4.shared.b16 {%0,%1,%2,%3}, [%4];" \
                 : "=r"(r0), "=r"(r1), "=r"(r2), "=r"(r3) : "r"(a))

#define LDSM4T(r0, r1, r2, r3, a) \
    asm volatile("ldmatrix.sync.aligned.m8n8.x4.trans.shared.b16 {%0,%1,%2,%3}, [%4];" \
                 : "=r"(r0), "=r"(r1), "=r"(r2), "=r"(r3) : "r"(a))

#define MMA16816(d, a0, a1, a2, a3, b0, b1) \
    asm volatile("mma.sync.aligned.m16n8k16.row.col.f32.bf16.bf16.f32 " \
                 "{%0,%1,%2,%3},{%4,%5,%6,%7},{%8,%9},{%0,%1,%2,%3};" \
                 : "+f"((d)[0]), "+f"((d)[1]), "+f"((d)[2]), "+f"((d)[3]) \
                 : "r"(a0), "r"(a1), "r"(a2), "r"(a3), "r"(b0), "r"(b1))

#define CP16(d, s) \
    asm volatile("cp.async.cg.shared.global [%0], [%1], 16;" :: "r"(d), "l"(s))
#define CP_COMMIT() asm volatile("cp.async.commit_group;" ::: "memory")
#define CP_WAIT(n)  asm volatile("cp.async.wait_group %0;" :: "n"(n) : "memory")

__device__ __forceinline__ void split2(float a, float b, uint32_t& h, uint32_t& l) {
    __nv_bfloat16 ha = __float2bfloat16_rn(a);
    __nv_bfloat16 hb = __float2bfloat16_rn(b);
    float la = a - __bfloat162float(ha);
    float lb = b - __bfloat162float(hb);
    __nv_bfloat162 H = __halves2bfloat162(ha, hb);
    __nv_bfloat162 L = __floats2bfloat162_rn(la, lb);
    h = *reinterpret_cast<uint32_t*>(&H);
    l = *reinterpret_cast<uint32_t*>(&L);
}
__device__ __forceinline__ void splitP(float a, float b, uint32_t& h, uint32_t& l) {
    const uint32_t ua = __float_as_uint(a), ub = __float_as_uint(b);
    h = __byte_perm(ua, ub, 0x7632);
    const float la = a - __uint_as_float(ua & 0xFFFF0000u);
    const float lb = b - __uint_as_float(ub & 0xFFFF0000u);
    __nv_bfloat162 L = __floats2bfloat162_rn(la, lb);
    l = *reinterpret_cast<uint32_t*>(&L);
}

// ---------------------------------------------------------------------------
__global__ __launch_bounds__(256)
void split_many(const float4* __restrict__ x0, const float4* __restrict__ x1,
                const float4* __restrict__ x2, const float4* __restrict__ x3,
                uint2* __restrict__ hb, uint2* __restrict__ lb, int n4)
{
    const int t = blockIdx.y;
    const float4* x = (t == 0) ? x0 : (t == 1) ? x1 : (t == 2) ? x2 : x3;
    uint2* h = hb + (size_t)t * n4;
    uint2* l = lb + (size_t)t * n4;
    for (int i = blockIdx.x * 256 + threadIdx.x; i < n4; i += gridDim.x * 256) {
        float4 v = x[i];
        uint2 hi, lo;
        split2(v.x, v.y, hi.x, lo.x);
        split2(v.z, v.w, hi.y, lo.y);
        h[i] = hi;
        l[i] = lo;
    }
}

// ---------------------------------------------------------------------------
// Split-bf16 GEMM body (R12 structure: BK=32, 3-stage cp.async, 96KB, occ 2).
// ---------------------------------------------------------------------------
#define PROJ_STG 32768
#define PROJ_SMEM 98304
#define NIT 32

__device__ __forceinline__ void proj_body(
    const __nv_bfloat16* __restrict__ Xh, const __nv_bfloat16* __restrict__ Xl,
    const __nv_bfloat16* __restrict__ Wh, const __nv_bfloat16* __restrict__ Wl,
    const float* __restrict__ bias, void* outA, void* outB,
    int mode, float scale, char* smc)
{
    const uint32_t sb = s2u(smc);
    const int tid = threadIdx.x;
    const int wid = tid >> 5;
    const int lane = tid & 31;

    const int m0 = blockIdx.y * 128;
    const int n0 = blockIdx.x * 128;
    const int wm = wid & 1;
    const int wn = wid >> 1;

    const int la_ = tid >> 6;
    const int pr = tid & 63;
    const __nv_bfloat16* gp = (la_ == 0) ? Xh : (la_ == 1) ? Xl : (la_ == 2) ? Wh : Wl;
    const int rb = (la_ < 2) ? m0 : n0;
    const char* gsrc = (const char*)(gp + (size_t)(rb + pr * 2) * DIM);
    const uint32_t ld0 = sb + (uint32_t)la_ * 8192u + (uint32_t)(pr * 2) * 64u;
    const uint32_t swr = ((uint32_t)pr & 3u) << 4;

    const int a_rin = (lane & 7) + ((lane >> 3) & 1) * 8;
    const uint32_t a_cbs = (uint32_t)((lane >> 4) * 16);
    const int b_rin = (lane & 7) + (lane >> 4) * 8;
    const uint32_t b_cbs = (uint32_t)(((lane >> 3) & 1) * 16);

    uint32_t aoff[4], arx[4];
#pragma unroll
    for (int t = 0; t < 4; t++) {
        const uint32_t r = (uint32_t)(wm * 64 + t * 16 + a_rin);
        aoff[t] = r * 64u;
        arx[t] = ((r >> 1) & 3u) << 4;
    }
    uint32_t boff[2], brx[2];
#pragma unroll
    for (int u = 0; u < 2; u++) {
        const uint32_t r = (uint32_t)(wn * 32 + u * 16 + b_rin);
        boff[u] = r * 64u;
        brx[u] = ((r >> 1) & 3u) << 4;
    }

    float acc[4][4][4];
#pragma unroll
    for (int i = 0; i < 4; i++)
#pragma unroll
        for (int j = 0; j < 4; j++)
#pragma unroll
            for (int c = 0; c < 4; c++) acc[i][j][c] = 0.f;

#pragma unroll
    for (int s = 0; s < 2; s++) {
        const char* s0 = gsrc + s * 64;
        const char* s1 = s0 + DIM * 2;
        const uint32_t d = ld0 + (uint32_t)(s * PROJ_STG);
#pragma unroll
        for (int i = 0; i < 4; i++) CP16(d + (((uint32_t)(i * 16)) ^ swr), s0 + i * 16);
#pragma unroll
        for (int i = 0; i < 4; i++) CP16(d + 64u + (((uint32_t)(i * 16)) ^ swr), s1 + i * 16);
        CP_COMMIT();
    }

    int stg = 0;
    for (int it = 0; it < NIT; it++) {
        if (it == NIT - 1) { CP_WAIT(0); } else { CP_WAIT(1); }
        __syncthreads();

        const uint32_t st = sb + (uint32_t)(stg * PROJ_STG);
        const uint32_t sAh = st, sAl = st + 8192u, sBh = st + 16384u, sBl = st + 24576u;

        uint32_t bh[2][4], bl[2][4], ah[4][4], al[4][4];
#pragma unroll
        for (int u = 0; u < 2; u++) {
            const uint32_t ad = boff[u] + (b_cbs ^ brx[u]);
            LDSM4(bh[u][0], bh[u][1], bh[u][2], bh[u][3], sBh + ad);
            LDSM4(bl[u][0], bl[u][1], bl[u][2], bl[u][3], sBl + ad);
        }
#pragma unroll
        for (int t = 0; t < 4; t++) {
            const uint32_t ad = aoff[t] + (a_cbs ^ arx[t]);
            LDSM4(ah[t][0], ah[t][1], ah[t][2], ah[t][3], sAh + ad);
            LDSM4(al[t][0], al[t][1], al[t][2], al[t][3], sAl + ad);
        }

        if (it + 2 < NIT) {
            const char* s0 = gsrc + (it + 2) * 64;
            const char* s1 = s0 + DIM * 2;
            const uint32_t d = ld0 + (uint32_t)(((it + 2) % 3) * PROJ_STG);
#pragma unroll
            for (int i = 0; i < 4; i++) CP16(d + (((uint32_t)(i * 16)) ^ swr), s0 + i * 16);
#pragma unroll
            for (int i = 0; i < 4; i++) CP16(d + 64u + (((uint32_t)(i * 16)) ^ swr), s1 + i * 16);
            CP_COMMIT();
        }

#pragma unroll
        for (int t = 0; t < 4; t++)
#pragma unroll
            for (int nt = 0; nt < 4; nt++) {
                const int u = nt >> 1, h2 = (nt & 1) * 2;
                MMA16816(acc[t][nt], ah[t][0], ah[t][1], ah[t][2], ah[t][3],
                         bh[u][h2], bh[u][h2 + 1]);
                MMA16816(acc[t][nt], ah[t][0], ah[t][1], ah[t][2], ah[t][3],
                         bl[u][h2], bl[u][h2 + 1]);
                MMA16816(acc[t][nt], al[t][0], al[t][1], al[t][2], al[t][3],
                         bh[u][h2], bh[u][h2 + 1]);
            }

#pragma unroll
        for (int u = 0; u < 2; u++) {
            const uint32_t ad = boff[u] + (((uint32_t)32 + b_cbs) ^ brx[u]);
            LDSM4(bh[u][0], bh[u][1], bh[u][2], bh[u][3], sBh + ad);
            LDSM4(bl[u][0], bl[u][1], bl[u][2], bl[u][3], sBl + ad);
        }
#pragma unroll
        for (int t = 0; t < 4; t++) {
            const uint32_t ad = aoff[t] + (((uint32_t)32 + a_cbs) ^ arx[t]);
            LDSM4(ah[t][0], ah[t][1], ah[t][2], ah[t][3], sAh + ad);
            LDSM4(al[t][0], al[t][1], al[t][2], al[t][3], sAl + ad);
        }
#pragma unroll
        for (int t = 0; t < 4; t++)
#pragma unroll
            for (int nt = 0; nt < 4; nt++) {
                const int u = nt >> 1, h2 = (nt & 1) * 2;
                MMA16816(acc[t][nt], ah[t][0], ah[t][1], ah[t][2], ah[t][3],
                         bh[u][h2], bh[u][h2 + 1]);
                MMA16816(acc[t][nt], ah[t][0], ah[t][1], ah[t][2], ah[t][3],
                         bl[u][h2], bl[u][h2 + 1]);
                MMA16816(acc[t][nt], al[t][0], al[t][1], al[t][2], al[t][3],
                         bh[u][h2], bh[u][h2 + 1]);
            }

        stg++;
        if (stg == 3) stg = 0;
    }

#pragma unroll
    for (int mt = 0; mt < 4; mt++) {
        const int m1 = m0 + wm * 64 + mt * 16 + (lane >> 2);
        const int m2 = m1 + 8;
#pragma unroll
        for (int nt = 0; nt < 4; nt++) {
            const int n = n0 + wn * 32 + nt * 8 + (lane & 3) * 2;
            const float b0v = bias[n], b1v = bias[n + 1];
            const float v00 = (acc[mt][nt][0] + b0v) * scale;
            const float v01 = (acc[mt][nt][1] + b1v) * scale;
            const float v10 = (acc[mt][nt][2] + b0v) * scale;
            const float v11 = (acc[mt][nt][3] + b1v) * scale;
            if (mode == 0) {
                float* out = (float*)outA;
                *(float2*)(out + (size_t)m1 * DIM + n) = make_float2(v00, v01);
                *(float2*)(out + (size_t)m2 * DIM + n) = make_float2(v10, v11);
            } else {
                const int h = n >> 6, hd = n & 63;
                const int b1i = m1 >> 11, s1 = m1 & 2047;
                const int b2i = m2 >> 11, s2 = m2 & 2047;
                __nv_bfloat16* oh = (__nv_bfloat16*)outA;
                __nv_bfloat16* ol = (__nv_bfloat16*)outB;
                uint32_t h0, l0, h1, l1;
                split2(v00, v01, h0, l0);
                split2(v10, v11, h1, l1);
                const size_t i1 = (((size_t)b1i * NHEAD + h) * SEQ + s1) * HDIM + hd;
                const size_t i2 = (((size_t)b2i * NHEAD + h) * SEQ + s2) * HDIM + hd;
                *(uint32_t*)(oh + i1) = h0;
                *(uint32_t*)(ol + i1) = l0;
                *(uint32_t*)(oh + i2) = h1;
                *(uint32_t*)(ol + i2) = l1;
            }
        }
    }
}

__global__ __launch_bounds__(256, 2)
void proj_qkv(const __nv_bfloat16* __restrict__ xh, const __nv_bfloat16* __restrict__ xl,
              const __nv_bfloat16* __restrict__ wh, const __nv_bfloat16* __restrict__ wl,
              const float* __restrict__ bq, const float* __restrict__ bk,
              const float* __restrict__ bv,
              __nv_bfloat16* qh, __nv_bfloat16* ql, __nv_bfloat16* kh, __nv_bfloat16* kl,
              __nv_bfloat16* vh, __nv_bfloat16* vl, float qscale)
{
    extern __shared__ __align__(128) char smc[];
    const int z = blockIdx.z;
    const size_t NXo = (size_t)MROWS * DIM;
    const size_t NWo = (size_t)DIM * DIM;
    const __nv_bfloat16* Xh = xh + (size_t)z * NXo;
    const __nv_bfloat16* Xl = xl + (size_t)z * NXo;
    const __nv_bfloat16* Wh = wh + (size_t)z * NWo;
    const __nv_bfloat16* Wl = wl + (size_t)z * NWo;
    const float* bias = (z == 0) ? bq : (z == 1) ? bk : bv;
    void* oA = (z == 0) ? (void*)qh : (z == 1) ? (void*)kh : (void*)vh;
    void* oB = (z == 0) ? (void*)ql : (z == 1) ? (void*)kl : (void*)vl;
    const float scale = (z == 0) ? qscale : 1.0f;
    proj_body(Xh, Xl, Wh, Wl, bias, oA, oB, 1, scale, smc);
}

__global__ __launch_bounds__(256, 2)
void proj_out(const __nv_bfloat16* __restrict__ Xh, const __nv_bfloat16* __restrict__ Xl,
              const __nv_bfloat16* __restrict__ Wh, const __nv_bfloat16* __restrict__ Wl,
              const float* __restrict__ bias, float* out)
{
    extern __shared__ __align__(128) char smc[];
    proj_body(Xh, Xl, Wh, Wl, bias, out, nullptr, 0, 1.0f, smc);
}

// ---------------------------------------------------------------------------
// Attention, 512 threads / 256 Q-rows per CTA (16 warps, each m16).
// Fixed-bias softmax, 3 smem stages, V via trans-ldmatrix. Occ 1, 160KB.
// ---------------------------------------------------------------------------
#define AQ_H 0
#define AQ_L 32768
#define ABUF0 65536
#define ABUF_SZ 32768
#define ATTN_SMEM 163840
#define NCHUNK (SEQ / 64)
#define MBIAS 12.0f

__global__ __launch_bounds__(512, 1)
void attn_mma(const __nv_bfloat16* __restrict__ qh_g, const __nv_bfloat16* __restrict__ ql_g,
              const __nv_bfloat16* __restrict__ kh_g, const __nv_bfloat16* __restrict__ kl_g,
              const __nv_bfloat16* __restrict__ vh_g, const __nv_bfloat16* __restrict__ vl_g,
              __nv_bfloat16* __restrict__ Oh, __nv_bfloat16* __restrict__ Ol)
{
    extern __shared__ __align__(128) char smc[];
    const uint32_t sb = s2u(smc);
    const int tid = threadIdx.x;
    const int wid = tid >> 5;          // 0..15
    const int lane = tid & 31;

    const int qt = blockIdx.x, h = blockIdx.y, b = blockIdx.z;
    const size_t bh = (size_t)(b * NHEAD + h);
    const int q0 = qt * 256;

    // Q group: 512 threads, a = tid>>8 (hi/lo), row = tid&255, 128B each
    {
        const int a = tid >> 8, r = tid & 255;
        const char* src = (const char*)((a == 0 ? qh_g : ql_g) + (bh * SEQ + q0 + r) * HDIM);
        const uint32_t dst = sb + (a == 0 ? AQ_H : AQ_L) + (uint32_t)r * 128u;
        const uint32_t swz = ((uint32_t)r & 7u) << 4;
#pragma unroll
        for (int i = 0; i < 8; i++)
            CP16(dst + ((uint32_t)(i * 16) ^ swz), src + i * 16);
        CP_COMMIT();
    }

    // chunk loader: group ca = tid>>7 (KH,KL,VH,VL); 128 threads per array,
    // each thread loads half a 128B row: row = (tid&127)>>1, half = (tid&1)*64
    const int ca = tid >> 7;
    const int cr = (tid & 127) >> 1;
    const uint32_t chalf = (uint32_t)((tid & 1) * 64);
    const __nv_bfloat16* gpc = (ca == 0) ? kh_g : (ca == 1) ? kl_g : (ca == 2) ? vh_g : vl_g;
    const char* csrc0 = (const char*)(gpc + (bh * SEQ + cr) * HDIM) + chalf;
    const size_t cstep = (size_t)64 * HDIM * 2;
    const uint32_t cdst0 = sb + ABUF0 + (uint32_t)ca * 8192u + (uint32_t)cr * 128u;
    const uint32_t cswz = ((uint32_t)cr & 7u) << 4;

    // chunks 0,1
#pragma unroll
    for (int s = 0; s < 2; s++) {
        const char* src = csrc0 + (size_t)s * cstep;
        const uint32_t dst = cdst0 + (uint32_t)(s * ABUF_SZ);
#pragma unroll
        for (int i = 0; i < 4; i++)
            CP16(dst + ((chalf + (uint32_t)(i * 16)) ^ cswz), src + i * 16);
        CP_COMMIT();
    }

    CP_WAIT(2);   // Q done (chunks 0,1 may be outstanding)
    __syncthreads();

    const int arow = wid * 16 + (lane & 7) + ((lane >> 3) & 1) * 8;
    const uint32_t aswz = ((uint32_t)lane & 7u) << 4;
    uint32_t qfh[4][4], qfl[4][4];
#pragma unroll
    for (int kt = 0; kt < 4; kt++) {
        const uint32_t cb = (uint32_t)(kt * 32 + (lane >> 4) * 16);
        const uint32_t ad = (uint32_t)arow * 128u + (cb ^ aswz);
        LDSM4(qfh[kt][0], qfh[kt][1], qfh[kt][2], qfh[kt][3], sb + AQ_H + ad);
        LDSM4(qfl[kt][0], qfl[kt][1], qfl[kt][2], qfl[kt][3], sb + AQ_L + ad);
    }

    const int brow = (lane & 7) + (lane >> 4) * 8;
    const uint32_t bswz = ((uint32_t)lane & 7u) << 4;
    const uint32_t bcbs = (uint32_t)(((lane >> 3) & 1) * 16);

    // V trans-ldmatrix geometry
    const uint32_t vrow_in = (uint32_t)(lane & 15);
    const uint32_t vcb = (uint32_t)((lane >> 4) * 16);

    float oacc[8][4];
#pragma unroll
    for (int t = 0; t < 8; t++)
#pragma unroll
        for (int j = 0; j < 4; j++) oacc[t][j] = 0.f;
    float l1 = 0.f, l2 = 0.f;

    int stg = 0;
    for (int c = 0; c < NCHUNK; c++) {
        if (c == NCHUNK - 1) { CP_WAIT(0); } else { CP_WAIT(1); }
        __syncthreads();

        const uint32_t kb_h = sb + ABUF0 + (uint32_t)(stg * ABUF_SZ);
        const uint32_t kb_l = kb_h + 8192u;
        const uint32_t vb_h = kb_h + 16384u;
        const uint32_t vb_l = kb_h + 24576u;

        // ---- S = Q K^T ----
        float sc[8][4];
#pragma unroll
        for (int t = 0; t < 8; t++)
#pragma unroll
            for (int j = 0; j < 4; j++) sc[t][j] = 0.f;

#pragma unroll
        for (int kt = 0; kt < 4; kt++) {
            uint32_t kfh[4][4], kfl[4][4];
#pragma unroll
            for (int u = 0; u < 4; u++) {
                const uint32_t ad = (uint32_t)(16 * u + brow) * 128u +
                                    (((uint32_t)(kt * 32) + bcbs) ^ bswz);
                LDSM4(kfh[u][0], kfh[u][1], kfh[u][2], kfh[u][3], kb_h + ad);
                LDSM4(kfl[u][0], kfl[u][1], kfl[u][2], kfl[u][3], kb_l + ad);
            }
#pragma unroll
            for (int nt = 0; nt < 8; nt++) {
                const int u = nt >> 1, h2 = (nt & 1) * 2;
                MMA16816(sc[nt], qfh[kt][0], qfh[kt][1], qfh[kt][2], qfh[kt][3],
                         kfh[u][h2], kfh[u][h2 + 1]);
                MMA16816(sc[nt], qfh[kt][0], qfh[kt][1], qfh[kt][2], qfh[kt][3],
                         kfl[u][h2], kfl[u][h2 + 1]);
                MMA16816(sc[nt], qfl[kt][0], qfl[kt][1], qfl[kt][2], qfl[kt][3],
                         kfh[u][h2], kfh[u][h2 + 1]);
            }
        }

        // prefetch chunk c+2
        if (c + 2 < NCHUNK) {
            const char* src = csrc0 + (size_t)(c + 2) * cstep;
            int s2i = stg + 2;
            if (s2i >= 3) s2i -= 3;
            const uint32_t dst = cdst0 + (uint32_t)(s2i * ABUF_SZ);
#pragma unroll
            for (int i = 0; i < 4; i++)
                CP16(dst + ((chalf + (uint32_t)(i * 16)) ^ cswz), src + i * 16);
            CP_COMMIT();
        }

        // ---- fixed-bias softmax: P = 2^(S - MBIAS) ----
#pragma unroll
        for (int t = 0; t < 8; t++) {
            sc[t][0] = ex2f(sc[t][0] - MBIAS);
            sc[t][1] = ex2f(sc[t][1] - MBIAS);
            sc[t][2] = ex2f(sc[t][2] - MBIAS);
            sc[t][3] = ex2f(sc[t][3] - MBIAS);
            l1 += sc[t][0] + sc[t][1];
            l2 += sc[t][2] + sc[t][3];
        }

        // ---- O += P V (trans ldmatrix for V) ----
#pragma unroll
        for (int kt = 0; kt < 4; kt++) {
            uint32_t ph[4], pl[4];
            splitP(sc[2 * kt][0], sc[2 * kt][1], ph[0], pl[0]);
            splitP(sc[2 * kt][2], sc[2 * kt][3], ph[1], pl[1]);
            splitP(sc[2 * kt + 1][0], sc[2 * kt + 1][1], ph[2], pl[2]);
            splitP(sc[2 * kt + 1][2], sc[2 * kt + 1][3], ph[3], pl[3]);

            const uint32_t vrbase = (uint32_t)(kt * 16) + vrow_in;
#pragma unroll
            for (int u = 0; u < 4; u++) {
                uint32_t vh4[4], vl4[4];
                const uint32_t ad = vrbase * 128u +
                                    (((uint32_t)(u * 32) + vcb) ^ bswz);
                LDSM4T(vh4[0], vh4[1], vh4[2], vh4[3], vb_h + ad);
                LDSM4T(vl4[0], vl4[1], vl4[2], vl4[3], vb_l + ad);
                MMA16816(oacc[2 * u],     ph[0], ph[1], ph[2], ph[3], vh4[0], vh4[1]);
                MMA16816(oacc[2 * u],     ph[0], ph[1], ph[2], ph[3], vl4[0], vl4[1]);
                MMA16816(oacc[2 * u],     pl[0], pl[1], pl[2], pl[3], vh4[0], vh4[1]);
                MMA16816(oacc[2 * u + 1], ph[0], ph[1], ph[2], ph[3], vh4[2], vh4[3]);
                MMA16816(oacc[2 * u + 1], ph[0], ph[1], ph[2], ph[3], vl4[2], vl4[3]);
                MMA16816(oacc[2 * u + 1], pl[0], pl[1], pl[2], pl[3], vh4[2], vh4[3]);
            }
        }

        stg++;
        if (stg == 3) stg = 0;
    }

    l1 += __shfl_xor_sync(0xffffffffu, l1, 1);
    l1 += __shfl_xor_sync(0xffffffffu, l1, 2);
    l2 += __shfl_xor_sync(0xffffffffu, l2, 1);
    l2 += __shfl_xor_sync(0xffffffffu, l2, 2);
    const float inv1 = 1.f / l1, inv2 = 1.f / l2;

    const int r1 = q0 + wid * 16 + (lane >> 2);
    const size_t i1 = ((size_t)b * SEQ + r1) * DIM + h * HDIM + (lane & 3) * 2;
    const size_t i2 = i1 + (size_t)8 * DIM;
#pragma unroll
    for (int t = 0; t < 8; t++) {
        uint32_t hh, ll;
        split2(oacc[t][0] * inv1, oacc[t][1] * inv1, hh, ll);
        *(uint32_t*)(Oh + i1 + t * 8) = hh;
        *(uint32_t*)(Ol + i1 + t * 8) = ll;
        split2(oacc[t][2] * inv2, oacc[t][3] * inv2, hh, ll);
        *(uint32_t*)(Oh + i2 + t * 8) = hh;
        *(uint32_t*)(Ol + i2 + t * 8) = ll;
    }
}

// ---------------------------------------------------------------------------
extern "C" void kernel_launch(void* const* d_in, const int* in_sizes, int n_in,
                              void* d_out, int out_size)
{
    const float* query = (const float*)d_in[0];
    const float* key   = (const float*)d_in[1];
    const float* value = (const float*)d_in[2];
    const float* Wq = (const float*)d_in[3];
    const float* bq = (const float*)d_in[4];
    const float* Wk = (const float*)d_in[5];
    const float* bk = (const float*)d_in[6];
    const float* Wv = (const float*)d_in[7];
    const float* bv = (const float*)d_in[8];
    const float* Wo = (const float*)d_in[9];
    const float* bo = (const float*)d_in[10];
    float* out = (float*)d_out;

    __nv_bfloat16 *xh, *xl, *wh, *wl;
    __nv_bfloat16 *qh, *ql, *kh, *kl, *vh, *vl, *ath, *atl;
    cudaGetSymbolAddress((void**)&xh, g_xh);
    cudaGetSymbolAddress((void**)&xl, g_xl);
    cudaGetSymbolAddress((void**)&wh, g_wh);
    cudaGetSymbolAddress((void**)&wl, g_wl);
    cudaGetSymbolAddress((void**)&qh, g_qh);
    cudaGetSymbolAddress((void**)&ql, g_ql);
    cudaGetSymbolAddress((void**)&kh, g_kh);
    cudaGetSymbolAddress((void**)&kl, g_kl);
    cudaGetSymbolAddress((void**)&vh, g_vh);
    cudaGetSymbolAddress((void**)&vl, g_vl);
    cudaGetSymbolAddress((void**)&ath, g_ath);
    cudaGetSymbolAddress((void**)&atl, g_atl);

    cudaFuncSetAttribute(proj_qkv, cudaFuncAttributeMaxDynamicSharedMemorySize, PROJ_SMEM);
    cudaFuncSetAttribute(proj_out, cudaFuncAttributeMaxDynamicSharedMemorySize, PROJ_SMEM);
    cudaFuncSetAttribute(attn_mma, cudaFuncAttributeMaxDynamicSharedMemorySize, ATTN_SMEM);

    const int NX = MROWS * DIM;
    const int NW = DIM * DIM;
    {
        dim3 gx(2048, 3);
        split_many<<<gx, 256>>>((const float4*)query, (const float4*)key,
                                (const float4*)value, (const float4*)value,
                                (uint2*)xh, (uint2*)xl, NX / 4);
        dim3 gw(512, 4);
        split_many<<<gw, 256>>>((const float4*)Wq, (const float4*)Wk,
                                (const float4*)Wv, (const float4*)Wo,
                                (uint2*)wh, (uint2*)wl, NW / 4);
    }

    const float QSCALE = 0.125f * 1.44269504f;
    dim3 pg3(DIM / 128, MROWS / 128, 3);
    proj_qkv<<<pg3, 256, PROJ_SMEM>>>(xh, xl, wh, wl, bq, bk, bv,
                                      qh, ql, kh, kl, vh, vl, QSCALE);

    dim3 ag(SEQ / 256, NHEAD, BBATCH);   // (8, 16, 4) = 512 CTAs
    attn_mma<<<ag, 512, ATTN_SMEM>>>(qh, ql, kh, kl, vh, vl, ath, atl);

    dim3 pg(DIM / 128, MROWS / 128);
    proj_out<<<pg, 256, PROJ_SMEM>>>(ath, atl, wh + (size_t)3 * NW, wl + (size_t)3 * NW,
                                     bo, out);
}